// round 16
// baseline (speedup 1.0000x reference)
#include <cuda_runtime.h>
#include <cuda_bf16.h>
#include <math.h>
#include <stdint.h>

#define TOK   4096
#define HD    1024
#define DD    2752
#define NEXP  8
#define NSLOT (TOK*2)
#define BM 256
#define BN 64
#define BK 32
#define NTHR 512

typedef __nv_bfloat16  bf16;
typedef __nv_bfloat162 bf162;

#define NE_ ((size_t)NEXP * HD * DD)
#define NS_ ((size_t)HD * DD)

// ---------------- scratch (device globals: allocation-free) ----------------
__device__ int   g_topk_idx[NSLOT];
__device__ float g_topk_w[NSLOT];
__device__ int   g_cnt[NEXP];
__device__ int   g_list[NEXP][TOK];
__device__ float g_out_r[(size_t)NSLOT * HD];

#define AL16 __align__(16)
__device__ AL16 bf16 g_x_hi[(size_t)TOK * HD];
__device__ AL16 bf16 g_x_lo[(size_t)TOK * HD];
__device__ AL16 bf16 g_hr_hi[(size_t)NSLOT * DD];
__device__ AL16 bf16 g_hr_lo[(size_t)NSLOT * DD];
__device__ AL16 bf16 g_hs_hi[(size_t)TOK * DD];
__device__ AL16 bf16 g_hs_lo[(size_t)TOK * DD];
__device__ AL16 bf16 g_eg_hi[NE_];
__device__ AL16 bf16 g_eg_lo[NE_];
__device__ AL16 bf16 g_eu_hi[NE_];
__device__ AL16 bf16 g_eu_lo[NE_];
__device__ AL16 bf16 g_ed_hi[NE_];
__device__ AL16 bf16 g_ed_lo[NE_];
__device__ AL16 bf16 g_sg_hi[NS_];
__device__ AL16 bf16 g_sg_lo[NS_];
__device__ AL16 bf16 g_su_hi[NS_];
__device__ AL16 bf16 g_su_lo[NS_];
__device__ AL16 bf16 g_sd_hi[NS_];
__device__ AL16 bf16 g_sd_lo[NS_];

// ---------------- PTX helpers ----------------------------------------------
__device__ __forceinline__ uint32_t smem_u32(const void* p) {
    uint32_t a;
    asm("{ .reg .u64 t; cvta.to.shared.u64 t, %1; cvt.u32.u64 %0, t; }"
        : "=r"(a) : "l"(p));
    return a;
}
#define SWZ(o)   ((uint32_t)(o) ^ ((((uint32_t)(o)) >> 3) & 0x70u))   // 128B rows
#define SWZ64(o) ((uint32_t)(o) ^ ((((uint32_t)(o)) >> 3) & 0x30u))   // 64B rows

#define CP16(dst, src) \
    asm volatile("cp.async.cg.shared.global [%0], [%1], 16;" :: "r"(dst), "l"(src))
#define CP_COMMIT() asm volatile("cp.async.commit_group;" ::: "memory")
#define CP_WAIT2()  asm volatile("cp.async.wait_group 2;" ::: "memory")
#define CP_WAIT1()  asm volatile("cp.async.wait_group 1;" ::: "memory")
#define CP_WAIT0()  asm volatile("cp.async.wait_group 0;" ::: "memory")

__device__ __forceinline__ void ldsm_x4(uint32_t* r, uint32_t a) {
    asm volatile("ldmatrix.sync.aligned.m8n8.x4.shared.b16 {%0,%1,%2,%3}, [%4];"
                 : "=r"(r[0]), "=r"(r[1]), "=r"(r[2]), "=r"(r[3]) : "r"(a));
}
__device__ __forceinline__ void ldsm_x4t(uint32_t* r, uint32_t a) {
    asm volatile("ldmatrix.sync.aligned.m8n8.x4.trans.shared.b16 {%0,%1,%2,%3}, [%4];"
                 : "=r"(r[0]), "=r"(r[1]), "=r"(r[2]), "=r"(r[3]) : "r"(a));
}
__device__ __forceinline__ void mma16816(float* c, const uint32_t* a,
                                         uint32_t b0, uint32_t b1) {
    asm volatile(
        "mma.sync.aligned.m16n8k16.row.col.f32.bf16.bf16.f32 "
        "{%0,%1,%2,%3}, {%4,%5,%6,%7}, {%8,%9}, {%0,%1,%2,%3};"
        : "+f"(c[0]), "+f"(c[1]), "+f"(c[2]), "+f"(c[3])
        : "r"(a[0]), "r"(a[1]), "r"(a[2]), "r"(a[3]), "r"(b0), "r"(b1));
}

__device__ __forceinline__ void splitb(float x, bf16& h, bf16& l) {
    h = __float2bfloat16(x);
    l = __float2bfloat16(x - __bfloat162float(h));
}

__device__ __forceinline__ void split_store4(const float* src, bf16* hi, bf16* lo,
                                             size_t off) {
    float4 v = *(const float4*)(src + off);
    bf16 h0, l0, h1, l1, h2, l2, h3, l3;
    splitb(v.x, h0, l0); splitb(v.y, h1, l1);
    splitb(v.z, h2, l2); splitb(v.w, h3, l3);
    bf162* ph = (bf162*)(hi + off);
    bf162* pl = (bf162*)(lo + off);
    ph[0] = bf162(h0, h1); ph[1] = bf162(h2, h3);
    pl[0] = bf162(l0, l1); pl[1] = bf162(l2, l3);
}

// ---------------- 1. conv: ffn1 weights ------------------------------------
__global__ void conv_w1(const float* __restrict__ eg, const float* __restrict__ eu,
                        const float* __restrict__ sg, const float* __restrict__ su)
{
    size_t i = ((size_t)blockIdx.x * blockDim.x + threadIdx.x) * 4;
    if (i < NE_)                 { split_store4(eg, g_eg_hi, g_eg_lo, i); return; }
    i -= NE_;
    if (i < NE_)                 { split_store4(eu, g_eu_hi, g_eu_lo, i); return; }
    i -= NE_;
    if (i < NS_)                 { split_store4(sg, g_sg_hi, g_sg_lo, i); return; }
    i -= NS_;
    if (i < NS_)                 { split_store4(su, g_su_hi, g_su_lo, i); return; }
}

// ---------------- 2. conv: ffn2 weights ------------------------------------
__global__ void conv_w2(const float* __restrict__ ed, const float* __restrict__ sd)
{
    size_t i = ((size_t)blockIdx.x * blockDim.x + threadIdx.x) * 4;
    if (i < NE_)                 { split_store4(ed, g_ed_hi, g_ed_lo, i); return; }
    i -= NE_;
    if (i < NS_)                 { split_store4(sd, g_sd_hi, g_sd_lo, i); return; }
}

// ---------------- 3. gating (fused x split, zeroes g_cnt) -------------------
__global__ void gate_kernel(const float* __restrict__ x,
                            const float* __restrict__ gw)
{
    int gwarp = (blockIdx.x * blockDim.x + threadIdx.x) >> 5;
    int lane  = threadIdx.x & 31;
    if (gwarp >= TOK) return;
    if (gwarp == 0 && lane < NEXP) g_cnt[lane] = 0;

    const float* xr = x + (size_t)gwarp * HD;
    float acc[NEXP];
#pragma unroll
    for (int e = 0; e < NEXP; e++) acc[e] = 0.f;

    for (int h0 = lane * 4; h0 < HD; h0 += 128) {
        float4 v = *(const float4*)(xr + h0);
#pragma unroll
        for (int e = 0; e < NEXP; e++) {
            const float* gr = gw + e * HD + h0;
            acc[e] += v.x * gr[0] + v.y * gr[1] + v.z * gr[2] + v.w * gr[3];
        }
        bf16 h0b, l0b, h1b, l1b, h2b, l2b, h3b, l3b;
        splitb(v.x, h0b, l0b); splitb(v.y, h1b, l1b);
        splitb(v.z, h2b, l2b); splitb(v.w, h3b, l3b);
        size_t off = (size_t)gwarp * HD + h0;
        bf162* ph = (bf162*)(g_x_hi + off);
        bf162* pl = (bf162*)(g_x_lo + off);
        ph[0] = bf162(h0b, h1b); ph[1] = bf162(h2b, h3b);
        pl[0] = bf162(l0b, l1b); pl[1] = bf162(l2b, l3b);
    }
#pragma unroll
    for (int e = 0; e < NEXP; e++) {
#pragma unroll
        for (int o = 16; o > 0; o >>= 1)
            acc[e] += __shfl_xor_sync(0xffffffffu, acc[e], o);
    }

    if (lane == 0) {
        float m = acc[0];
#pragma unroll
        for (int e = 1; e < NEXP; e++) m = fmaxf(m, acc[e]);
        float p[NEXP];
#pragma unroll
        for (int e = 0; e < NEXP; e++) p[e] = expf(acc[e] - m);
        int i0 = 0;
#pragma unroll
        for (int e = 1; e < NEXP; e++) if (p[e] > p[i0]) i0 = e;
        int i1 = (i0 == 0) ? 1 : 0;
#pragma unroll
        for (int e = 0; e < NEXP; e++)
            if (e != i0 && p[e] > p[i1]) i1 = e;
        float s2 = p[i0] + p[i1] + 1e-30f;
        g_topk_idx[2 * gwarp + 0] = i0;
        g_topk_idx[2 * gwarp + 1] = i1;
        g_topk_w[2 * gwarp + 0] = p[i0] / s2;
        g_topk_w[2 * gwarp + 1] = p[i1] / s2;
    }
}

// ---------------- 4. binning via atomics ------------------------------------
__global__ void bin_kernel()
{
    int s = blockIdx.x * blockDim.x + threadIdx.x;
    if (s >= NSLOT) return;
    int e = g_topk_idx[s];
    int pos = atomicAdd(&g_cnt[e], 1);
    g_list[e][pos] = s;
}

// ---------------- 5. FFN1: 3-stage BK=32 pipeline ---------------------------
// stage 48KB: A_hi 0 (16K), A_lo 16K, Bg_hi 32K (4K), Bg_lo 36K, Bu_hi 40K, Bu_lo 44K
#define F1_STAGE 49152
#define NK1 (HD / BK)   // 32

__global__ __launch_bounds__(NTHR, 1)
void ffn1_mma()
{
    int ez = blockIdx.z;
    bool routed = ez < NEXP;
    int cnt = routed ? g_cnt[ez] : TOK;
    int mt = blockIdx.y, nt = blockIdx.x;
    if (mt * BM >= cnt) return;

    extern __shared__ __align__(1024) char smem[];
    __shared__ int rowtok[BM];
    __shared__ int rowslot[BM];

    int tid = threadIdx.x, lane = tid & 31, wid = tid >> 5;
    for (int r = tid; r < BM; r += NTHR) {
        int i = mt * BM + r, t = -1, s = -1;
        if (i < cnt) {
            if (routed) { s = g_list[ez][i]; t = s >> 1; }
            else        { s = i; t = i; }
        }
        rowtok[r] = t; rowslot[r] = s;
    }
    __syncthreads();

    const bf16* bgh = routed ? (g_eg_hi + (size_t)ez * HD * DD) : g_sg_hi;
    const bf16* bgl = routed ? (g_eg_lo + (size_t)ez * HD * DD) : g_sg_lo;
    const bf16* buh = routed ? (g_eu_hi + (size_t)ez * HD * DD) : g_su_hi;
    const bf16* bul = routed ? (g_eu_lo + (size_t)ez * HD * DD) : g_su_lo;

    uint32_t sbase = smem_u32(smem);
    float ag[2][4][4], au[2][4][4];
#pragma unroll
    for (int b = 0; b < 2; b++)
#pragma unroll
        for (int c = 0; c < 4; c++)
#pragma unroll
            for (int d = 0; d < 4; d++) { ag[b][c][d] = 0.f; au[b][c][d] = 0.f; }

    // A: 64B rows, SW64. 1024 16B-slots per array (256 rows x 4 chunks).
    // B: 128B rows, SW128. 256 slots per array (32 rows x 8 chunks).
    int a_r0 = tid >> 2,          a_c0 = tid & 3;          // slot tid
    int a_r1 = (tid + 512) >> 2,  a_c1 = (tid + 512) & 3;  // slot tid+512
    bool isGate = tid < 256;
    int b_slot = tid & 255;
    int b_r = b_slot >> 3, b_c = b_slot & 7;
    const bf16* bWh = isGate ? bgh : buh;
    const bf16* bWl = isGate ? bgl : bul;
    uint32_t b_dsth = (isGate ? 32768u : 40960u) + SWZ(b_r * 128 + b_c * 16);
    uint32_t b_dstl = (isGate ? 36864u : 45056u) + SWZ(b_r * 128 + b_c * 16);
    uint32_t a_d0 = SWZ64(a_r0 * 64 + a_c0 * 16);
    uint32_t a_d1 = SWZ64(a_r1 * 64 + a_c1 * 16);
    int t0 = rowtok[a_r0], t1 = rowtok[a_r1];
    const bf16* aph0 = g_x_hi + (size_t)(t0 < 0 ? 0 : t0) * HD + a_c0 * 8;
    const bf16* apl0 = g_x_lo + (size_t)(t0 < 0 ? 0 : t0) * HD + a_c0 * 8;
    const bf16* aph1 = g_x_hi + (size_t)(t1 < 0 ? 0 : t1) * HD + a_c1 * 8;
    const bf16* apl1 = g_x_lo + (size_t)(t1 < 0 ? 0 : t1) * HD + a_c1 * 8;
    const bf16* bph = bWh + (size_t)b_r * DD + nt * BN + b_c * 8;
    const bf16* bpl = bWl + (size_t)b_r * DD + nt * BN + b_c * 8;

    auto load_stage = [&](int ks) {
        uint32_t s0 = sbase + (uint32_t)(ks % 3) * F1_STAGE;
        int k0 = ks * BK;
        CP16(s0 + a_d0,         aph0 + k0);
        CP16(s0 + 16384 + a_d0, apl0 + k0);
        CP16(s0 + a_d1,         aph1 + k0);
        CP16(s0 + 16384 + a_d1, apl1 + k0);
        CP16(s0 + b_dsth, bph + (size_t)k0 * DD);
        CP16(s0 + b_dstl, bpl + (size_t)k0 * DD);
        CP_COMMIT();
    };

    int wm = wid & 7, wn = wid >> 3;   // 8 m-warps x 2 n-warps; warp tile 32x32
    load_stage(0); load_stage(1);
    for (int ks = 0; ks < NK1; ks++) {
        if (ks + 2 < NK1)      { load_stage(ks + 2); CP_WAIT2(); }
        else if (ks + 1 < NK1) { CP_WAIT1(); }
        else                   { CP_WAIT0(); }
        __syncthreads();
        uint32_t s0 = sbase + (uint32_t)(ks % 3) * F1_STAGE;
#pragma unroll
        for (int kk = 0; kk < 2; kk++) {
            uint32_t ah[2][4], al[2][4];
#pragma unroll
            for (int mi = 0; mi < 2; mi++) {
                int row = wm * 32 + mi * 16 + (lane & 15);
                uint32_t ad = SWZ64(row * 64 + kk * 32 + (lane >> 4) * 16);
                ldsm_x4(ah[mi], s0 + ad);
                ldsm_x4(al[mi], s0 + 16384 + ad);
            }
            int kr = kk * 16 + (lane & 15);
            uint32_t bd0 = SWZ(kr * 128 + (wn * 32 +  0) * 2 + (lane >> 4) * 16);
            uint32_t bd1 = SWZ(kr * 128 + (wn * 32 + 16) * 2 + (lane >> 4) * 16);

            // ---- gate ----
            {
                uint32_t bh[8], bl[8];
                ldsm_x4t(bh + 0, s0 + 32768 + bd0);
                ldsm_x4t(bh + 4, s0 + 32768 + bd1);
                ldsm_x4t(bl + 0, s0 + 36864 + bd0);
                ldsm_x4t(bl + 4, s0 + 36864 + bd1);
#pragma unroll
                for (int mi = 0; mi < 2; mi++)
#pragma unroll
                    for (int ni = 0; ni < 4; ni++) {
                        int j = (ni >> 1) * 4 + (ni & 1) * 2;
                        mma16816(ag[mi][ni], ah[mi], bh[j], bh[j + 1]);
                    }
#pragma unroll
                for (int mi = 0; mi < 2; mi++)
#pragma unroll
                    for (int ni = 0; ni < 4; ni++) {
                        int j = (ni >> 1) * 4 + (ni & 1) * 2;
                        mma16816(ag[mi][ni], ah[mi], bl[j], bl[j + 1]);
                    }
#pragma unroll
                for (int mi = 0; mi < 2; mi++)
#pragma unroll
                    for (int ni = 0; ni < 4; ni++) {
                        int j = (ni >> 1) * 4 + (ni & 1) * 2;
                        mma16816(ag[mi][ni], al[mi], bh[j], bh[j + 1]);
                    }
            }
            // ---- up ----
            {
                uint32_t bh[8], bl[8];
                ldsm_x4t(bh + 0, s0 + 40960 + bd0);
                ldsm_x4t(bh + 4, s0 + 40960 + bd1);
                ldsm_x4t(bl + 0, s0 + 45056 + bd0);
                ldsm_x4t(bl + 4, s0 + 45056 + bd1);
#pragma unroll
                for (int mi = 0; mi < 2; mi++)
#pragma unroll
                    for (int ni = 0; ni < 4; ni++) {
                        int j = (ni >> 1) * 4 + (ni & 1) * 2;
                        mma16816(au[mi][ni], ah[mi], bh[j], bh[j + 1]);
                    }
#pragma unroll
                for (int mi = 0; mi < 2; mi++)
#pragma unroll
                    for (int ni = 0; ni < 4; ni++) {
                        int j = (ni >> 1) * 4 + (ni & 1) * 2;
                        mma16816(au[mi][ni], ah[mi], bl[j], bl[j + 1]);
                    }
#pragma unroll
                for (int mi = 0; mi < 2; mi++)
#pragma unroll
                    for (int ni = 0; ni < 4; ni++) {
                        int j = (ni >> 1) * 4 + (ni & 1) * 2;
                        mma16816(au[mi][ni], al[mi], bh[j], bh[j + 1]);
                    }
            }
        }
        __syncthreads();
    }

    bf16* dhi = routed ? g_hr_hi : g_hs_hi;
    bf16* dlo = routed ? g_hr_lo : g_hs_lo;
#pragma unroll
    for (int mi = 0; mi < 2; mi++) {
        int rbase = wm * 32 + mi * 16 + (lane >> 2);
#pragma unroll
        for (int rr = 0; rr < 2; rr++) {
            int r = rbase + rr * 8;
            int s = rowslot[r];
            if (s < 0) continue;
            size_t rowoff = (size_t)s * DD + nt * BN + wn * 32 + (lane & 3) * 2;
#pragma unroll
            for (int ni = 0; ni < 4; ni++) {
                float g0 = ag[mi][ni][rr * 2 + 0], g1 = ag[mi][ni][rr * 2 + 1];
                float u0 = au[mi][ni][rr * 2 + 0], u1 = au[mi][ni][rr * 2 + 1];
                float h0 = g0 / (1.f + __expf(-g0)) * u0;
                float h1 = g1 / (1.f + __expf(-g1)) * u1;
                bf16 hh0, hl0, hh1, hl1;
                splitb(h0, hh0, hl0);
                splitb(h1, hh1, hl1);
                *(bf162*)(dhi + rowoff + ni * 8) = bf162(hh0, hh1);
                *(bf162*)(dlo + rowoff + ni * 8) = bf162(hl0, hl1);
            }
        }
    }
}

// ---------------- 6. FFN2: 3-stage BK=32 pipeline ---------------------------
// stage 40KB: A_hi 0 (16K), A_lo 16K, B_hi 32K (4K), B_lo 36K
#define F2_STAGE 40960
#define NK2 (DD / BK)   // 86

__global__ __launch_bounds__(NTHR, 1)
void ffn2_mma(float* __restrict__ out)
{
    int ez = blockIdx.z;
    bool routed = ez < NEXP;
    int cnt = routed ? g_cnt[ez] : TOK;
    int mt = blockIdx.y, nt = blockIdx.x;
    if (mt * BM >= cnt) return;

    extern __shared__ __align__(1024) char smem[];
    __shared__ int   rowslot[BM];
    __shared__ float roww[BM];

    int tid = threadIdx.x, lane = tid & 31, wid = tid >> 5;
    for (int r = tid; r < BM; r += NTHR) {
        int i = mt * BM + r, s = -1;
        float w = 0.f;
        if (i < cnt) {
            if (routed) { s = g_list[ez][i]; w = g_topk_w[s]; }
            else        { s = i; w = 1.f; }
        }
        rowslot[r] = s; roww[r] = w;
    }
    __syncthreads();

    const bf16* ahsrc = routed ? g_hr_hi : g_hs_hi;
    const bf16* alsrc = routed ? g_hr_lo : g_hs_lo;
    const bf16* bh_g  = routed ? (g_ed_hi + (size_t)ez * DD * HD) : g_sd_hi;
    const bf16* bl_g  = routed ? (g_ed_lo + (size_t)ez * DD * HD) : g_sd_lo;

    uint32_t sbase = smem_u32(smem);
    float acc[2][4][4];
#pragma unroll
    for (int b = 0; b < 2; b++)
#pragma unroll
        for (int c = 0; c < 4; c++)
#pragma unroll
            for (int d = 0; d < 4; d++) acc[b][c][d] = 0.f;

    int a_r0 = tid >> 2,          a_c0 = tid & 3;
    int a_r1 = (tid + 512) >> 2,  a_c1 = (tid + 512) & 3;
    bool isHi = tid < 256;
    int b_slot = tid & 255;
    int b_r = b_slot >> 3, b_c = b_slot & 7;
    uint32_t b_dst = (isHi ? 32768u : 36864u) + SWZ(b_r * 128 + b_c * 16);
    const bf16* bsrc = (isHi ? bh_g : bl_g) + (size_t)b_r * HD + nt * BN + b_c * 8;
    uint32_t a_d0 = SWZ64(a_r0 * 64 + a_c0 * 16);
    uint32_t a_d1 = SWZ64(a_r1 * 64 + a_c1 * 16);
    int s0r = rowslot[a_r0], s1r = rowslot[a_r1];
    const bf16* aph0 = ahsrc + (size_t)(s0r < 0 ? 0 : s0r) * DD + a_c0 * 8;
    const bf16* apl0 = alsrc + (size_t)(s0r < 0 ? 0 : s0r) * DD + a_c0 * 8;
    const bf16* aph1 = ahsrc + (size_t)(s1r < 0 ? 0 : s1r) * DD + a_c1 * 8;
    const bf16* apl1 = alsrc + (size_t)(s1r < 0 ? 0 : s1r) * DD + a_c1 * 8;

    auto load_stage = [&](int ks) {
        uint32_t s0 = sbase + (uint32_t)(ks % 3) * F2_STAGE;
        int k0 = ks * BK;
        CP16(s0 + a_d0,         aph0 + k0);
        CP16(s0 + 16384 + a_d0, apl0 + k0);
        CP16(s0 + a_d1,         aph1 + k0);
        CP16(s0 + 16384 + a_d1, apl1 + k0);
        CP16(s0 + b_dst, bsrc + (size_t)k0 * HD);
        CP_COMMIT();
    };

    int wm = wid & 7, wn = wid >> 3;
    load_stage(0); load_stage(1);
    for (int ks = 0; ks < NK2; ks++) {
        if (ks + 2 < NK2)      { load_stage(ks + 2); CP_WAIT2(); }
        else if (ks + 1 < NK2) { CP_WAIT1(); }
        else                   { CP_WAIT0(); }
        __syncthreads();
        uint32_t s0 = sbase + (uint32_t)(ks % 3) * F2_STAGE;
#pragma unroll
        for (int kk = 0; kk < 2; kk++) {
            uint32_t ah[2][4], al[2][4];
#pragma unroll
            for (int mi = 0; mi < 2; mi++) {
                int row = wm * 32 + mi * 16 + (lane & 15);
                uint32_t ad = SWZ64(row * 64 + kk * 32 + (lane >> 4) * 16);
                ldsm_x4(ah[mi], s0 + ad);
                ldsm_x4(al[mi], s0 + 16384 + ad);
            }
            int kr = kk * 16 + (lane & 15);
            uint32_t bd0 = SWZ(kr * 128 + (wn * 32 +  0) * 2 + (lane >> 4) * 16);
            uint32_t bd1 = SWZ(kr * 128 + (wn * 32 + 16) * 2 + (lane >> 4) * 16);
            uint32_t bh[8], bl[8];
            ldsm_x4t(bh + 0, s0 + 32768 + bd0);
            ldsm_x4t(bh + 4, s0 + 32768 + bd1);
            ldsm_x4t(bl + 0, s0 + 36864 + bd0);
            ldsm_x4t(bl + 4, s0 + 36864 + bd1);
#pragma unroll
            for (int mi = 0; mi < 2; mi++)
#pragma unroll
                for (int ni = 0; ni < 4; ni++) {
                    int j = (ni >> 1) * 4 + (ni & 1) * 2;
                    mma16816(acc[mi][ni], ah[mi], bh[j], bh[j + 1]);
                }
#pragma unroll
            for (int mi = 0; mi < 2; mi++)
#pragma unroll
                for (int ni = 0; ni < 4; ni++) {
                    int j = (ni >> 1) * 4 + (ni & 1) * 2;
                    mma16816(acc[mi][ni], ah[mi], bl[j], bl[j + 1]);
                }
#pragma unroll
            for (int mi = 0; mi < 2; mi++)
#pragma unroll
                for (int ni = 0; ni < 4; ni++) {
                    int j = (ni >> 1) * 4 + (ni & 1) * 2;
                    mma16816(acc[mi][ni], al[mi], bh[j], bh[j + 1]);
                }
        }
        __syncthreads();
    }

#pragma unroll
    for (int mi = 0; mi < 2; mi++) {
        int rbase = wm * 32 + mi * 16 + (lane >> 2);
#pragma unroll
        for (int rr = 0; rr < 2; rr++) {
            int r = rbase + rr * 8;
            int s = rowslot[r];
            if (s < 0) continue;
            float w = roww[r];
            size_t rowoff = (size_t)s * HD + nt * BN + wn * 32 + (lane & 3) * 2;
            float* dst = routed ? (g_out_r + rowoff) : (out + rowoff);
#pragma unroll
            for (int ni = 0; ni < 4; ni++) {
                float2 o;
                o.x = w * acc[mi][ni][rr * 2 + 0];
                o.y = w * acc[mi][ni][rr * 2 + 1];
                *(float2*)(dst + ni * 8) = o;
            }
        }
    }
}

// ---------------- 7. combine ------------------------------------------------
__global__ void combine_kernel(float* __restrict__ out)
{
    int idx = blockIdx.x * blockDim.x + threadIdx.x;
    int t = idx >> 10;
    int h = idx & (HD - 1);
    out[idx] += g_out_r[(size_t)(2 * t) * HD + h]
              + g_out_r[(size_t)(2 * t + 1) * HD + h];
}

// ---------------- launch ----------------------------------------------------
extern "C" void kernel_launch(void* const* d_in, const int* in_sizes, int n_in,
                              void* d_out, int out_size)
{
    (void)in_sizes; (void)n_in; (void)out_size;
    const float* x   = (const float*)d_in[0];
    const float* gw  = (const float*)d_in[1];
    const float* weg = (const float*)d_in[2];
    const float* weu = (const float*)d_in[3];
    const float* wed = (const float*)d_in[4];
    const float* swg = (const float*)d_in[5];
    const float* swu = (const float*)d_in[6];
    const float* swd = (const float*)d_in[7];
    float* out = (float*)d_out;

    static bool init = false;
    if (!init) {
        cudaFuncSetAttribute(ffn1_mma, cudaFuncAttributeMaxDynamicSharedMemorySize, 3 * F1_STAGE);
        cudaFuncSetAttribute(ffn2_mma, cudaFuncAttributeMaxDynamicSharedMemorySize, 3 * F2_STAGE);
        init = true;
    }

    const size_t nW1 = 2 * NE_ + 2 * NS_;
    const size_t nW2 = NE_ + NS_;

    conv_w1<<<(unsigned)((nW1 / 4 + 255) / 256), 256>>>(weg, weu, swg, swu);// 1
    gate_kernel<<<TOK / 4, 128>>>(x, gw);                                   // 2
    bin_kernel<<<NSLOT / 256, 256>>>();                                     // 3
    ffn1_mma<<<dim3(DD / BN, (TOK + BM - 1) / BM, NEXP + 1), NTHR, 3 * F1_STAGE>>>(); // 4 <- profiled
    conv_w2<<<(unsigned)((nW2 / 4 + 255) / 256), 256>>>(wed, swd);          // 5
    ffn2_mma<<<dim3(HD / BN, (TOK + BM - 1) / BM, NEXP + 1), NTHR, 3 * F2_STAGE>>>(out); // 6
    combine_kernel<<<(TOK * HD) / 256, 256>>>(out);                         // 7
}

// round 17
// speedup vs baseline: 1.1634x; 1.1634x over previous
#include <cuda_runtime.h>
#include <cuda_bf16.h>
#include <math.h>
#include <stdint.h>

#define TOK   4096
#define HD    1024
#define DD    2752
#define NEXP  8
#define NSLOT (TOK*2)
#define BM 256
#define BN 64
#define BN2 128
#define BK 64
#define NTHR 512

typedef __nv_bfloat16  bf16;
typedef __nv_bfloat162 bf162;

#define NE_ ((size_t)NEXP * HD * DD)
#define NS_ ((size_t)HD * DD)

// ---------------- scratch (device globals: allocation-free) ----------------
__device__ int   g_topk_idx[NSLOT];
__device__ float g_topk_w[NSLOT];
__device__ int   g_cnt[NEXP];
__device__ int   g_list[NEXP][TOK];
__device__ float g_out_r[(size_t)NSLOT * HD];

#define AL16 __align__(16)
__device__ AL16 bf16 g_x_hi[(size_t)TOK * HD];
__device__ AL16 bf16 g_x_lo[(size_t)TOK * HD];
__device__ AL16 bf16 g_hr_hi[(size_t)NSLOT * DD];
__device__ AL16 bf16 g_hr_lo[(size_t)NSLOT * DD];
__device__ AL16 bf16 g_hs_hi[(size_t)TOK * DD];
__device__ AL16 bf16 g_hs_lo[(size_t)TOK * DD];
__device__ AL16 bf16 g_eg_hi[NE_];
__device__ AL16 bf16 g_eg_lo[NE_];
__device__ AL16 bf16 g_eu_hi[NE_];
__device__ AL16 bf16 g_eu_lo[NE_];
__device__ AL16 bf16 g_ed_hi[NE_];
__device__ AL16 bf16 g_ed_lo[NE_];
__device__ AL16 bf16 g_sg_hi[NS_];
__device__ AL16 bf16 g_sg_lo[NS_];
__device__ AL16 bf16 g_su_hi[NS_];
__device__ AL16 bf16 g_su_lo[NS_];
__device__ AL16 bf16 g_sd_hi[NS_];
__device__ AL16 bf16 g_sd_lo[NS_];

// ---------------- PTX helpers ----------------------------------------------
__device__ __forceinline__ uint32_t smem_u32(const void* p) {
    uint32_t a;
    asm("{ .reg .u64 t; cvta.to.shared.u64 t, %1; cvt.u32.u64 %0, t; }"
        : "=r"(a) : "l"(p));
    return a;
}
#define SWZ(o) ((uint32_t)(o) ^ ((((uint32_t)(o)) >> 3) & 0x70u))

#define CP16(dst, src) \
    asm volatile("cp.async.cg.shared.global [%0], [%1], 16;" :: "r"(dst), "l"(src))
#define CP_COMMIT() asm volatile("cp.async.commit_group;" ::: "memory")
#define CP_WAIT1()  asm volatile("cp.async.wait_group 1;" ::: "memory")
#define CP_WAIT0()  asm volatile("cp.async.wait_group 0;" ::: "memory")

__device__ __forceinline__ void ldsm_x4(uint32_t* r, uint32_t a) {
    asm volatile("ldmatrix.sync.aligned.m8n8.x4.shared.b16 {%0,%1,%2,%3}, [%4];"
                 : "=r"(r[0]), "=r"(r[1]), "=r"(r[2]), "=r"(r[3]) : "r"(a));
}
__device__ __forceinline__ void ldsm_x4t(uint32_t* r, uint32_t a) {
    asm volatile("ldmatrix.sync.aligned.m8n8.x4.trans.shared.b16 {%0,%1,%2,%3}, [%4];"
                 : "=r"(r[0]), "=r"(r[1]), "=r"(r[2]), "=r"(r[3]) : "r"(a));
}
__device__ __forceinline__ void mma16816(float* c, const uint32_t* a,
                                         uint32_t b0, uint32_t b1) {
    asm volatile(
        "mma.sync.aligned.m16n8k16.row.col.f32.bf16.bf16.f32 "
        "{%0,%1,%2,%3}, {%4,%5,%6,%7}, {%8,%9}, {%0,%1,%2,%3};"
        : "+f"(c[0]), "+f"(c[1]), "+f"(c[2]), "+f"(c[3])
        : "r"(a[0]), "r"(a[1]), "r"(a[2]), "r"(a[3]), "r"(b0), "r"(b1));
}

__device__ __forceinline__ void splitb(float x, bf16& h, bf16& l) {
    h = __float2bfloat16(x);
    l = __float2bfloat16(x - __bfloat162float(h));
}

__device__ __forceinline__ void split_store4(const float* src, bf16* hi, bf16* lo,
                                             size_t off) {
    float4 v = *(const float4*)(src + off);
    bf16 h0, l0, h1, l1, h2, l2, h3, l3;
    splitb(v.x, h0, l0); splitb(v.y, h1, l1);
    splitb(v.z, h2, l2); splitb(v.w, h3, l3);
    bf162* ph = (bf162*)(hi + off);
    bf162* pl = (bf162*)(lo + off);
    ph[0] = bf162(h0, h1); ph[1] = bf162(h2, h3);
    pl[0] = bf162(l0, l1); pl[1] = bf162(l2, l3);
}

// ---------------- 1. conv: ALL weights fused --------------------------------
__global__ void conv_w(const float* __restrict__ eg, const float* __restrict__ eu,
                       const float* __restrict__ ed,
                       const float* __restrict__ sg, const float* __restrict__ su,
                       const float* __restrict__ sd)
{
    size_t i = ((size_t)blockIdx.x * blockDim.x + threadIdx.x) * 4;
    if (i < NE_)                 { split_store4(eg, g_eg_hi, g_eg_lo, i); return; }
    i -= NE_;
    if (i < NE_)                 { split_store4(eu, g_eu_hi, g_eu_lo, i); return; }
    i -= NE_;
    if (i < NE_)                 { split_store4(ed, g_ed_hi, g_ed_lo, i); return; }
    i -= NE_;
    if (i < NS_)                 { split_store4(sg, g_sg_hi, g_sg_lo, i); return; }
    i -= NS_;
    if (i < NS_)                 { split_store4(su, g_su_hi, g_su_lo, i); return; }
    i -= NS_;
    if (i < NS_)                 { split_store4(sd, g_sd_hi, g_sd_lo, i); return; }
}

// ---------------- 2. gating (fused x split, zeroes g_cnt) -------------------
__global__ void gate_kernel(const float* __restrict__ x,
                            const float* __restrict__ gw)
{
    int gwarp = (blockIdx.x * blockDim.x + threadIdx.x) >> 5;
    int lane  = threadIdx.x & 31;
    if (gwarp >= TOK) return;
    if (gwarp == 0 && lane < NEXP) g_cnt[lane] = 0;

    const float* xr = x + (size_t)gwarp * HD;
    float acc[NEXP];
#pragma unroll
    for (int e = 0; e < NEXP; e++) acc[e] = 0.f;

    for (int h0 = lane * 4; h0 < HD; h0 += 128) {
        float4 v = *(const float4*)(xr + h0);
#pragma unroll
        for (int e = 0; e < NEXP; e++) {
            const float* gr = gw + e * HD + h0;
            acc[e] += v.x * gr[0] + v.y * gr[1] + v.z * gr[2] + v.w * gr[3];
        }
        bf16 h0b, l0b, h1b, l1b, h2b, l2b, h3b, l3b;
        splitb(v.x, h0b, l0b); splitb(v.y, h1b, l1b);
        splitb(v.z, h2b, l2b); splitb(v.w, h3b, l3b);
        size_t off = (size_t)gwarp * HD + h0;
        bf162* ph = (bf162*)(g_x_hi + off);
        bf162* pl = (bf162*)(g_x_lo + off);
        ph[0] = bf162(h0b, h1b); ph[1] = bf162(h2b, h3b);
        pl[0] = bf162(l0b, l1b); pl[1] = bf162(l2b, l3b);
    }
#pragma unroll
    for (int e = 0; e < NEXP; e++) {
#pragma unroll
        for (int o = 16; o > 0; o >>= 1)
            acc[e] += __shfl_xor_sync(0xffffffffu, acc[e], o);
    }

    if (lane == 0) {
        float m = acc[0];
#pragma unroll
        for (int e = 1; e < NEXP; e++) m = fmaxf(m, acc[e]);
        float p[NEXP];
#pragma unroll
        for (int e = 0; e < NEXP; e++) p[e] = expf(acc[e] - m);
        int i0 = 0;
#pragma unroll
        for (int e = 1; e < NEXP; e++) if (p[e] > p[i0]) i0 = e;
        int i1 = (i0 == 0) ? 1 : 0;
#pragma unroll
        for (int e = 0; e < NEXP; e++)
            if (e != i0 && p[e] > p[i1]) i1 = e;
        float s2 = p[i0] + p[i1] + 1e-30f;
        g_topk_idx[2 * gwarp + 0] = i0;
        g_topk_idx[2 * gwarp + 1] = i1;
        g_topk_w[2 * gwarp + 0] = p[i0] / s2;
        g_topk_w[2 * gwarp + 1] = p[i1] / s2;
    }
}

// ---------------- 3. binning via atomics ------------------------------------
__global__ void bin_kernel()
{
    int s = blockIdx.x * blockDim.x + threadIdx.x;
    if (s >= NSLOT) return;
    int e = g_topk_idx[s];
    int pos = atomicAdd(&g_cnt[e], 1);
    g_list[e][pos] = s;
}

// ---------------- 4. FFN1: R13 config (BK=64, 2-stage, 512 thr) ------------
// stage 96KB: A_hi 0, A_lo 32K, Bg_hi 64K, Bg_lo 72K, Bu_hi 80K, Bu_lo 88K
#define F1_STAGE 98304
#define NK1 (HD / BK)   // 16

__global__ __launch_bounds__(NTHR, 1)
void ffn1_mma()
{
    int ez = blockIdx.z;
    bool routed = ez < NEXP;
    int cnt = routed ? g_cnt[ez] : TOK;
    int mt = blockIdx.y, nt = blockIdx.x;
    if (mt * BM >= cnt) return;

    extern __shared__ __align__(1024) char smem[];
    __shared__ int rowtok[BM];
    __shared__ int rowslot[BM];

    int tid = threadIdx.x, lane = tid & 31, wid = tid >> 5;
    for (int r = tid; r < BM; r += NTHR) {
        int i = mt * BM + r, t = -1, s = -1;
        if (i < cnt) {
            if (routed) { s = g_list[ez][i]; t = s >> 1; }
            else        { s = i; t = i; }
        }
        rowtok[r] = t; rowslot[r] = s;
    }
    __syncthreads();

    const bf16* bgh = routed ? (g_eg_hi + (size_t)ez * HD * DD) : g_sg_hi;
    const bf16* bgl = routed ? (g_eg_lo + (size_t)ez * HD * DD) : g_sg_lo;
    const bf16* buh = routed ? (g_eu_hi + (size_t)ez * HD * DD) : g_su_hi;
    const bf16* bul = routed ? (g_eu_lo + (size_t)ez * HD * DD) : g_su_lo;

    uint32_t sbase = smem_u32(smem);
    float ag[2][4][4], au[2][4][4];
#pragma unroll
    for (int b = 0; b < 2; b++)
#pragma unroll
        for (int c = 0; c < 4; c++)
#pragma unroll
            for (int d = 0; d < 4; d++) { ag[b][c][d] = 0.f; au[b][c][d] = 0.f; }

    auto load_stage = [&](int ks) {
        uint32_t s0 = sbase + (uint32_t)(ks & 1) * F1_STAGE;
        int k0 = ks * BK;
#pragma unroll
        for (int i = 0; i < 4; i++) {
            int slot = i * NTHR + tid;
            int r = slot >> 3, c = slot & 7;
            int t = rowtok[r];
            size_t off = (size_t)(t < 0 ? 0 : t) * HD + k0 + c * 8;
            uint32_t d = SWZ(r * 128 + c * 16);
            CP16(s0 + d,         g_x_hi + off);
            CP16(s0 + 32768 + d, g_x_lo + off);
        }
        {
            int r = tid >> 3, c = tid & 7;
            size_t off = (size_t)(k0 + r) * DD + nt * BN + c * 8;
            uint32_t d = SWZ(r * 128 + c * 16);
            CP16(s0 + 65536 + d, bgh + off);
            CP16(s0 + 73728 + d, bgl + off);
            CP16(s0 + 81920 + d, buh + off);
            CP16(s0 + 90112 + d, bul + off);
        }
        CP_COMMIT();
    };

    int wm = wid & 7, wn = wid >> 3;   // 8 m-warps x 2 n-warps; warp tile 32x32
    load_stage(0);
    for (int ks = 0; ks < NK1; ks++) {
        if (ks + 1 < NK1) { load_stage(ks + 1); CP_WAIT1(); }
        else              { CP_WAIT0(); }
        __syncthreads();
        uint32_t s0 = sbase + (uint32_t)(ks & 1) * F1_STAGE;
#pragma unroll
        for (int k16 = 0; k16 < 4; k16++) {
            uint32_t ah[2][4], al[2][4];
#pragma unroll
            for (int mi = 0; mi < 2; mi++) {
                int row = wm * 32 + mi * 16 + (lane & 15);
                uint32_t ad = SWZ(row * 128 + k16 * 32 + (lane >> 4) * 16);
                ldsm_x4(ah[mi], s0 + ad);
                ldsm_x4(al[mi], s0 + 32768 + ad);
            }
            int kr = k16 * 16 + (lane & 15);
            uint32_t bd0 = SWZ(kr * 128 + (wn * 32 +  0) * 2 + (lane >> 4) * 16);
            uint32_t bd1 = SWZ(kr * 128 + (wn * 32 + 16) * 2 + (lane >> 4) * 16);

            // ---- gate ----
            {
                uint32_t bh[8], bl[8];
                ldsm_x4t(bh + 0, s0 + 65536 + bd0);
                ldsm_x4t(bh + 4, s0 + 65536 + bd1);
                ldsm_x4t(bl + 0, s0 + 73728 + bd0);
                ldsm_x4t(bl + 4, s0 + 73728 + bd1);
#pragma unroll
                for (int mi = 0; mi < 2; mi++)
#pragma unroll
                    for (int ni = 0; ni < 4; ni++) {
                        int j = (ni >> 1) * 4 + (ni & 1) * 2;
                        mma16816(ag[mi][ni], ah[mi], bh[j], bh[j + 1]);
                    }
#pragma unroll
                for (int mi = 0; mi < 2; mi++)
#pragma unroll
                    for (int ni = 0; ni < 4; ni++) {
                        int j = (ni >> 1) * 4 + (ni & 1) * 2;
                        mma16816(ag[mi][ni], ah[mi], bl[j], bl[j + 1]);
                    }
#pragma unroll
                for (int mi = 0; mi < 2; mi++)
#pragma unroll
                    for (int ni = 0; ni < 4; ni++) {
                        int j = (ni >> 1) * 4 + (ni & 1) * 2;
                        mma16816(ag[mi][ni], al[mi], bh[j], bh[j + 1]);
                    }
            }
            // ---- up ----
            {
                uint32_t bh[8], bl[8];
                ldsm_x4t(bh + 0, s0 + 81920 + bd0);
                ldsm_x4t(bh + 4, s0 + 81920 + bd1);
                ldsm_x4t(bl + 0, s0 + 90112 + bd0);
                ldsm_x4t(bl + 4, s0 + 90112 + bd1);
#pragma unroll
                for (int mi = 0; mi < 2; mi++)
#pragma unroll
                    for (int ni = 0; ni < 4; ni++) {
                        int j = (ni >> 1) * 4 + (ni & 1) * 2;
                        mma16816(au[mi][ni], ah[mi], bh[j], bh[j + 1]);
                    }
#pragma unroll
                for (int mi = 0; mi < 2; mi++)
#pragma unroll
                    for (int ni = 0; ni < 4; ni++) {
                        int j = (ni >> 1) * 4 + (ni & 1) * 2;
                        mma16816(au[mi][ni], ah[mi], bl[j], bl[j + 1]);
                    }
#pragma unroll
                for (int mi = 0; mi < 2; mi++)
#pragma unroll
                    for (int ni = 0; ni < 4; ni++) {
                        int j = (ni >> 1) * 4 + (ni & 1) * 2;
                        mma16816(au[mi][ni], al[mi], bh[j], bh[j + 1]);
                    }
            }
        }
        __syncthreads();
    }

    bf16* dhi = routed ? g_hr_hi : g_hs_hi;
    bf16* dlo = routed ? g_hr_lo : g_hs_lo;
#pragma unroll
    for (int mi = 0; mi < 2; mi++) {
        int rbase = wm * 32 + mi * 16 + (lane >> 2);
#pragma unroll
        for (int rr = 0; rr < 2; rr++) {
            int r = rbase + rr * 8;
            int s = rowslot[r];
            if (s < 0) continue;
            size_t rowoff = (size_t)s * DD + nt * BN + wn * 32 + (lane & 3) * 2;
#pragma unroll
            for (int ni = 0; ni < 4; ni++) {
                float g0 = ag[mi][ni][rr * 2 + 0], g1 = ag[mi][ni][rr * 2 + 1];
                float u0 = au[mi][ni][rr * 2 + 0], u1 = au[mi][ni][rr * 2 + 1];
                float h0 = g0 / (1.f + __expf(-g0)) * u0;
                float h1 = g1 / (1.f + __expf(-g1)) * u1;
                bf16 hh0, hl0, hh1, hl1;
                splitb(h0, hh0, hl0);
                splitb(h1, hh1, hl1);
                *(bf162*)(dhi + rowoff + ni * 8) = bf162(hh0, hh1);
                *(bf162*)(dlo + rowoff + ni * 8) = bf162(hl0, hl1);
            }
        }
    }
}

// ---------------- 5. FFN2: BN=128, BK=64, 2-stage ---------------------------
// stage 96KB: A_hi 0 (32K), A_lo 32K, B_hi 64K (16K: 2 panels of 8K), B_lo 80K
#define F2_STAGE 98304
#define NK2 (DD / BK)   // 43

__global__ __launch_bounds__(NTHR, 1)
void ffn2_mma(float* __restrict__ out)
{
    int ez = blockIdx.z;
    bool routed = ez < NEXP;
    int cnt = routed ? g_cnt[ez] : TOK;
    int mt = blockIdx.y, nt = blockIdx.x;
    if (mt * BM >= cnt) return;

    extern __shared__ __align__(1024) char smem[];
    __shared__ int   rowslot[BM];
    __shared__ float roww[BM];

    int tid = threadIdx.x, lane = tid & 31, wid = tid >> 5;
    for (int r = tid; r < BM; r += NTHR) {
        int i = mt * BM + r, s = -1;
        float w = 0.f;
        if (i < cnt) {
            if (routed) { s = g_list[ez][i]; w = g_topk_w[s]; }
            else        { s = i; w = 1.f; }
        }
        rowslot[r] = s; roww[r] = w;
    }
    __syncthreads();

    const bf16* ahsrc = routed ? g_hr_hi : g_hs_hi;
    const bf16* alsrc = routed ? g_hr_lo : g_hs_lo;
    const bf16* bh_g  = routed ? (g_ed_hi + (size_t)ez * DD * HD) : g_sd_hi;
    const bf16* bl_g  = routed ? (g_ed_lo + (size_t)ez * DD * HD) : g_sd_lo;

    uint32_t sbase = smem_u32(smem);
    float acc[2][8][4];
#pragma unroll
    for (int b = 0; b < 2; b++)
#pragma unroll
        for (int c = 0; c < 8; c++)
#pragma unroll
            for (int d = 0; d < 4; d++) acc[b][c][d] = 0.f;

    auto load_stage = [&](int ks) {
        uint32_t s0 = sbase + (uint32_t)(ks & 1) * F2_STAGE;
        int k0 = ks * BK;
#pragma unroll
        for (int i = 0; i < 4; i++) {          // A: 2048 slots (256r x 8c)
            int slot = i * NTHR + tid;
            int r = slot >> 3, c = slot & 7;
            int s = rowslot[r];
            size_t off = (size_t)(s < 0 ? 0 : s) * DD + k0 + c * 8;
            uint32_t d = SWZ(r * 128 + c * 16);
            CP16(s0 + d,         ahsrc + off);
            CP16(s0 + 32768 + d, alsrc + off);
        }
#pragma unroll
        for (int i = 0; i < 2; i++) {          // B: 1024 slots (64r x 16c), 2 panels
            int slot = i * NTHR + tid;
            int r = slot >> 4, c = slot & 15;
            size_t off = (size_t)(k0 + r) * HD + nt * BN2 + c * 8;
            uint32_t d = (uint32_t)(c >> 3) * 8192 + SWZ(r * 128 + (c & 7) * 16);
            CP16(s0 + 65536 + d, bh_g + off);
            CP16(s0 + 81920 + d, bl_g + off);
        }
        CP_COMMIT();
    };

    int wm = wid & 7, wn = wid >> 3;   // 8 m-warps x 2 n-warps; warp tile 32x64
    load_stage(0);
    for (int ks = 0; ks < NK2; ks++) {
        if (ks + 1 < NK2) { load_stage(ks + 1); CP_WAIT1(); }
        else              { CP_WAIT0(); }
        __syncthreads();
        uint32_t s0 = sbase + (uint32_t)(ks & 1) * F2_STAGE;
        uint32_t pan = (uint32_t)wn * 8192;    // n-warp's 64-col panel
#pragma unroll
        for (int k16 = 0; k16 < 4; k16++) {
            uint32_t ah[2][4], al[2][4];
#pragma unroll
            for (int mi = 0; mi < 2; mi++) {
                int row = wm * 32 + mi * 16 + (lane & 15);
                uint32_t ad = SWZ(row * 128 + k16 * 32 + (lane >> 4) * 16);
                ldsm_x4(ah[mi], s0 + ad);
                ldsm_x4(al[mi], s0 + 32768 + ad);
            }
            int kr = k16 * 16 + (lane & 15);
#pragma unroll
            for (int h = 0; h < 2; h++) {      // two 32-col halves of the panel
                uint32_t bd0 = pan + SWZ(kr * 128 + (h * 32 +  0) * 2 + (lane >> 4) * 16);
                uint32_t bd1 = pan + SWZ(kr * 128 + (h * 32 + 16) * 2 + (lane >> 4) * 16);
                uint32_t bh[8], bl[8];
                ldsm_x4t(bh + 0, s0 + 65536 + bd0);
                ldsm_x4t(bh + 4, s0 + 65536 + bd1);
                ldsm_x4t(bl + 0, s0 + 81920 + bd0);
                ldsm_x4t(bl + 4, s0 + 81920 + bd1);
#pragma unroll
                for (int mi = 0; mi < 2; mi++)
#pragma unroll
                    for (int ni = 0; ni < 4; ni++) {
                        int j = (ni >> 1) * 4 + (ni & 1) * 2;
                        mma16816(acc[mi][h * 4 + ni], ah[mi], bh[j], bh[j + 1]);
                    }
#pragma unroll
                for (int mi = 0; mi < 2; mi++)
#pragma unroll
                    for (int ni = 0; ni < 4; ni++) {
                        int j = (ni >> 1) * 4 + (ni & 1) * 2;
                        mma16816(acc[mi][h * 4 + ni], ah[mi], bl[j], bl[j + 1]);
                    }
#pragma unroll
                for (int mi = 0; mi < 2; mi++)
#pragma unroll
                    for (int ni = 0; ni < 4; ni++) {
                        int j = (ni >> 1) * 4 + (ni & 1) * 2;
                        mma16816(acc[mi][h * 4 + ni], al[mi], bh[j], bh[j + 1]);
                    }
            }
        }
        __syncthreads();
    }

#pragma unroll
    for (int mi = 0; mi < 2; mi++) {
        int rbase = wm * 32 + mi * 16 + (lane >> 2);
#pragma unroll
        for (int rr = 0; rr < 2; rr++) {
            int r = rbase + rr * 8;
            int s = rowslot[r];
            if (s < 0) continue;
            float w = roww[r];
            size_t rowoff = (size_t)s * HD + nt * BN2 + wn * 64 + (lane & 3) * 2;
            float* dst = routed ? (g_out_r + rowoff) : (out + rowoff);
#pragma unroll
            for (int q = 0; q < 8; q++) {
                int coladd = (q >> 2) * 32 + (q & 3) * 8;
                float2 o;
                o.x = w * acc[mi][q][rr * 2 + 0];
                o.y = w * acc[mi][q][rr * 2 + 1];
                *(float2*)(dst + coladd) = o;
            }
        }
    }
}

// ---------------- 6. combine ------------------------------------------------
__global__ void combine_kernel(float* __restrict__ out)
{
    int idx = blockIdx.x * blockDim.x + threadIdx.x;
    int t = idx >> 10;
    int h = idx & (HD - 1);
    out[idx] += g_out_r[(size_t)(2 * t) * HD + h]
              + g_out_r[(size_t)(2 * t + 1) * HD + h];
}

// ---------------- launch ----------------------------------------------------
extern "C" void kernel_launch(void* const* d_in, const int* in_sizes, int n_in,
                              void* d_out, int out_size)
{
    (void)in_sizes; (void)n_in; (void)out_size;
    const float* x   = (const float*)d_in[0];
    const float* gw  = (const float*)d_in[1];
    const float* weg = (const float*)d_in[2];
    const float* weu = (const float*)d_in[3];
    const float* wed = (const float*)d_in[4];
    const float* swg = (const float*)d_in[5];
    const float* swu = (const float*)d_in[6];
    const float* swd = (const float*)d_in[7];
    float* out = (float*)d_out;

    static bool init = false;
    if (!init) {
        cudaFuncSetAttribute(ffn1_mma, cudaFuncAttributeMaxDynamicSharedMemorySize, 2 * F1_STAGE);
        cudaFuncSetAttribute(ffn2_mma, cudaFuncAttributeMaxDynamicSharedMemorySize, 2 * F2_STAGE);
        init = true;
    }

    const size_t nW = 3 * NE_ + 3 * NS_;

    conv_w<<<(unsigned)((nW / 4 + 255) / 256), 256>>>(weg, weu, wed, swg, swu, swd); // 1
    gate_kernel<<<TOK / 4, 128>>>(x, gw);                                            // 2
    bin_kernel<<<NSLOT / 256, 256>>>();                                              // 3
    ffn1_mma<<<dim3(DD / BN, (TOK + BM - 1) / BM, NEXP + 1), NTHR, 2 * F1_STAGE>>>();// 4 <- profiled
    ffn2_mma<<<dim3(HD / BN2, (TOK + BM - 1) / BM, NEXP + 1), NTHR, 2 * F2_STAGE>>>(out); // 5
    combine_kernel<<<(TOK * HD) / 256, 256>>>(out);                                  // 6
}